// round 10
// baseline (speedup 1.0000x reference)
#include <cuda_runtime.h>
#include <cuda_bf16.h>
#include <cstdint>
#include <math_constants.h>

// ---------------- problem constants ----------------
static constexpr int NN  = 40000;     // nodes
static constexpr int NE  = 1280000;   // edges
static constexpr int DF  = 1024;      // input feat
static constexpr int HID = 64;        // hidden
static constexpr int NC  = 40;        // classes

// ---------------- device scratch ----------------
__device__ float g_H1[(size_t)NN * HID];   // x @ W1
__device__ float g_H2[(size_t)NN * NC];    // relu(agg1 + b1) @ W2
__device__ float g_dinv[NN];
__device__ int   g_deg[NN];                // in-degree; zero-invariant across launches
__device__ int   g_rowptr[NN];             // CSR start per node
__device__ int   g_cursor[NN];
__device__ int   g_rowtmp[NN];             // inclusive scan, pre-base
__device__ int   g_bsum[160];
__device__ int2  g_edge[NE];               // (src, weight-bits) grouped by dst
__device__ __nv_bfloat16 g_W1h[(size_t)HID * DF];  // W1^T hi, [n][k]
__device__ __nv_bfloat16 g_W1l[(size_t)HID * DF];  // W1^T lo, [n][k]

// ---------------- helpers ----------------
__device__ __forceinline__ uint32_t smem_to_u32(const void* p) {
    uint32_t a;
    asm("{ .reg .u64 t; cvta.to.shared.u64 t, %1; cvt.u32.u64 %0, t; }" : "=r"(a) : "l"(p));
    return a;
}
__device__ __forceinline__ uint32_t bfbits(__nv_bfloat16 h) {
    return (uint32_t)__bfloat16_as_ushort(h);
}
#define LDSM4(r, addr) \
    asm volatile("ldmatrix.sync.aligned.m8n8.x4.shared.b16 {%0,%1,%2,%3}, [%4];" \
                 : "=r"((r)[0]), "=r"((r)[1]), "=r"((r)[2]), "=r"((r)[3]) : "r"(addr))
__device__ __forceinline__ void mma16816(float* c, const uint32_t* a, uint32_t b0, uint32_t b1) {
    asm volatile(
        "mma.sync.aligned.m16n8k16.row.col.f32.bf16.bf16.f32 "
        "{%0,%1,%2,%3}, {%4,%5,%6,%7}, {%8,%9}, {%0,%1,%2,%3};"
        : "+f"(c[0]), "+f"(c[1]), "+f"(c[2]), "+f"(c[3])
        : "r"(a[0]), "r"(a[1]), "r"(a[2]), "r"(a[3]), "r"(b0), "r"(b1));
}

// ---------------- prep: fused W1 split + degree histogram (block-range split) ----------------
static constexpr int WSPLIT_NB = (DF * HID) / 256;       // 256
static constexpr int HIST_NB   = (NE + 255) / 256;       // 5000
__global__ void k_prep(const int* __restrict__ col, const float* __restrict__ W1) {
    int b = blockIdx.x;
    if (b < WSPLIT_NB) {
        int idx = b * 256 + threadIdx.x;
        int k = idx >> 6, n = idx & 63;
        float w = W1[idx];
        __nv_bfloat16 hi = __float2bfloat16(w);
        float lo = w - __bfloat162float(hi);
        g_W1h[(size_t)n * DF + k] = hi;
        g_W1l[(size_t)n * DF + k] = __float2bfloat16(lo);
    } else {
        int e = (b - WSPLIT_NB) * 256 + threadIdx.x;
        if (e < NE) atomicAdd(&g_deg[col[e]], 1);
    }
}

// ---------------- CSR build: scanA + fused scanC + fill ----------------
static constexpr int SCAN_NB = (NN + 255) / 256;  // 157
__global__ void k_scanA() {
    __shared__ int s[256];
    int i = blockIdx.x * 256 + threadIdx.x;
    int v = (i < NN) ? g_deg[i] : 0;
    s[threadIdx.x] = v;
    __syncthreads();
#pragma unroll
    for (int off = 1; off < 256; off <<= 1) {
        int t = (threadIdx.x >= off) ? s[threadIdx.x - off] : 0;
        __syncthreads();
        s[threadIdx.x] += t;
        __syncthreads();
    }
    if (i < NN) g_rowtmp[i] = s[threadIdx.x];
    if (threadIdx.x == 255) g_bsum[blockIdx.x] = s[255];
}
// scanC with inline block-base reduction (replaces scanB)
__global__ void k_scanC() {
    __shared__ int wsum[8];
    __shared__ int s_base;
    const int t = threadIdx.x, lane = t & 31, wid = t >> 5;
    const int b = blockIdx.x;
    int v = (t < SCAN_NB && t < b) ? g_bsum[t] : 0;
#pragma unroll
    for (int off = 16; off; off >>= 1) v += __shfl_down_sync(0xffffffffu, v, off);
    if (lane == 0) wsum[wid] = v;
    __syncthreads();
    if (t == 0) {
        int base = 0;
#pragma unroll
        for (int k = 0; k < 8; k++) base += wsum[k];
        s_base = base;
    }
    __syncthreads();
    int i = b * 256 + t;
    if (i < NN) {
        int d = g_deg[i];
        int start = s_base + g_rowtmp[i] - d;
        g_rowptr[i] = start;
        g_cursor[i] = start;
        g_dinv[i] = rsqrtf((float)(d + 1));  // +1 self loop
    }
}
__global__ void k_fill(const int* __restrict__ row, const int* __restrict__ col) {
    int e = blockIdx.x * blockDim.x + threadIdx.x;
    if (e >= NE) return;
    int r = __ldg(row + e), c = __ldg(col + e);
    int p = atomicAdd(&g_cursor[c], 1);
    float w = __ldg(g_dinv + r) * __ldg(g_dinv + c);
    g_edge[p] = make_int2(r, __float_as_int(w));
}

// ---------------- GEMM1: mma.sync bf16 hi/lo compensated, coalesced A, plain stores ----------------
static constexpr int SA_STRIDE = 72;                     // bf16 elems per row
static constexpr int SAH_OFF = 0;
static constexpr int SAL_OFF = 128 * SA_STRIDE * 2;      // 18432
static constexpr int SBH_OFF = SAL_OFF * 2;              // 36864
static constexpr int SBL_OFF = SBH_OFF + 64 * SA_STRIDE * 2;  // 46080
static constexpr int SM_TOTAL = SBL_OFF + 64 * SA_STRIDE * 2; // 55296

__global__ void __launch_bounds__(256, 2) k_gemm1(const float* __restrict__ x) {
    extern __shared__ char sm[];
    const uint32_t smb = smem_to_u32(sm);
    const int t = threadIdx.x;
    const int lane = t & 31, w = t >> 5;
    const int m0 = blockIdx.x * 128;

    // Coalesced A mapping: thread t -> rows {t>>4 + 16i}, 16B col block c4 = t&15.
    const int r0t = t >> 4;
    const int c4  = t & 15;
    const float4* xb = (const float4*)x;
    bool rv[8];
    size_t rbase[8];
    uint32_t aDst[8];
#pragma unroll
    for (int i = 0; i < 8; i++) {
        int rowg = m0 + r0t + 16 * i;
        rv[i] = rowg < NN;
        rbase[i] = (size_t)rowg * 256 + c4;  // float4 units
        aDst[i] = (uint32_t)((r0t + 16 * i) * (SA_STRIDE * 2) + c4 * 8);
    }

    const uint32_t aLd = smb +
        (uint32_t)((w * 16 + (lane & 7) + ((lane >> 3) & 1) * 8) * (SA_STRIDE * 2) +
                   (lane >> 4) * 16);
    const uint32_t bLd = smb +
        (uint32_t)((((lane >> 4) * 8) + (lane & 7)) * (SA_STRIDE * 2) +
                   ((lane >> 3) & 1) * 16);

    float acc[8][4];
#pragma unroll
    for (int j = 0; j < 8; j++)
#pragma unroll
        for (int q = 0; q < 4; q++) acc[j][q] = 0.f;

    float4 pf[8];
#pragma unroll
    for (int i = 0; i < 8; i++)
        pf[i] = rv[i] ? __ldg(xb + rbase[i]) : make_float4(0.f, 0.f, 0.f, 0.f);

    for (int kc = 0; kc < 16; kc++) {
        // ---- B global loads first (latency overlaps A convert ALU) ----
        uint2 bh[4], bl[4];
#pragma unroll
        for (int j = 0; j < 4; j++) {
            int lin = t + j * 256;
            int n = lin >> 4, q = lin & 15;
            size_t src = (size_t)n * DF + kc * 64 + q * 4;
            bh[j] = __ldg((const uint2*)(g_W1h + src));
            bl[j] = __ldg((const uint2*)(g_W1l + src));
        }
        // ---- convert prefetched A: f32 -> bf16 hi/lo ----
#pragma unroll
        for (int i = 0; i < 8; i++) {
            float4 v = pf[i];
            __nv_bfloat16 hx = __float2bfloat16(v.x), hy = __float2bfloat16(v.y);
            __nv_bfloat16 hz = __float2bfloat16(v.z), hw = __float2bfloat16(v.w);
            *(uint2*)(sm + SAH_OFF + aDst[i]) =
                make_uint2(bfbits(hx) | (bfbits(hy) << 16), bfbits(hz) | (bfbits(hw) << 16));
            __nv_bfloat16 lx = __float2bfloat16(v.x - __bfloat162float(hx));
            __nv_bfloat16 ly = __float2bfloat16(v.y - __bfloat162float(hy));
            __nv_bfloat16 lz = __float2bfloat16(v.z - __bfloat162float(hz));
            __nv_bfloat16 lw = __float2bfloat16(v.w - __bfloat162float(hw));
            *(uint2*)(sm + SAL_OFF + aDst[i]) =
                make_uint2(bfbits(lx) | (bfbits(ly) << 16), bfbits(lz) | (bfbits(lw) << 16));
        }
        // ---- store B ----
#pragma unroll
        for (int j = 0; j < 4; j++) {
            int lin = t + j * 256;
            int n = lin >> 4, q = lin & 15;
            uint32_t dst = (uint32_t)(n * (SA_STRIDE * 2) + q * 8);
            *(uint2*)(sm + SBH_OFF + dst) = bh[j];
            *(uint2*)(sm + SBL_OFF + dst) = bl[j];
        }
        __syncthreads();

        // ---- prefetch next A chunk (overlaps MMA) ----
        if (kc < 15) {
#pragma unroll
            for (int i = 0; i < 8; i++)
                pf[i] = rv[i] ? __ldg(xb + rbase[i] + (kc + 1) * 16)
                              : make_float4(0.f, 0.f, 0.f, 0.f);
        }

        // ---- compute: 4 k16 steps x 8 ntiles x 3 passes ----
#pragma unroll
        for (int ks = 0; ks < 4; ks++) {
            uint32_t ah[4], al[4];
            LDSM4(ah, aLd + SAH_OFF + ks * 32);
            LDSM4(al, aLd + SAL_OFF + ks * 32);
#pragma unroll
            for (int jp = 0; jp < 4; jp++) {
                uint32_t vh[4], vl[4];
                LDSM4(vh, bLd + SBH_OFF + jp * (16 * SA_STRIDE * 2) + ks * 32);
                LDSM4(vl, bLd + SBL_OFF + jp * (16 * SA_STRIDE * 2) + ks * 32);
                mma16816(acc[2 * jp],     ah, vh[0], vh[1]);
                mma16816(acc[2 * jp],     ah, vl[0], vl[1]);
                mma16816(acc[2 * jp],     al, vh[0], vh[1]);
                mma16816(acc[2 * jp + 1], ah, vh[2], vh[3]);
                mma16816(acc[2 * jp + 1], ah, vl[2], vl[3]);
                mma16816(acc[2 * jp + 1], al, vh[2], vh[3]);
            }
        }
        __syncthreads();
    }

    // ---- epilogue ----
    const int g = lane >> 2, tig = lane & 3;
    const int r0 = m0 + w * 16 + g;
    const int r1 = r0 + 8;
#pragma unroll
    for (int nt = 0; nt < 8; nt++) {
        int c = nt * 8 + tig * 2;
        if (r0 < NN) *(float2*)(g_H1 + (size_t)r0 * 64 + c) = make_float2(acc[nt][0], acc[nt][1]);
        if (r1 < NN) *(float2*)(g_H1 + (size_t)r1 * 64 + c) = make_float2(acc[nt][2], acc[nt][3]);
    }
}

// ---------------- gather1 + relu + bias + GEMM2 fused (warp per node) ----------------
__global__ void __launch_bounds__(256) k_gather1(const float* __restrict__ b1,
                                                 const float* __restrict__ W2) {
    __shared__ float sW[HID * NC];   // 10240 B
    __shared__ float sO[8][HID];     // 2048 B
    for (int i = threadIdx.x; i < HID * NC; i += 256) sW[i] = __ldg(W2 + i);
    __syncthreads();

    const int w = threadIdx.x >> 5, lane = threadIdx.x & 31;
    const int n = blockIdx.x * 8 + w;

    float di = __ldg(g_dinv + n);
    float2 acc = __ldg((const float2*)(g_H1 + (size_t)n * 64) + lane);
    acc.x *= di * di; acc.y *= di * di;

    const int start = __ldg(g_rowptr + n);
    const int cnt   = __ldg(g_deg + n);
    const int2* ep = g_edge + start;
    int i = 0;
    for (; i + 8 <= cnt; i += 8) {
        int2 e[8];
#pragma unroll
        for (int u = 0; u < 8; u++) e[u] = __ldg(ep + i + u);
        float2 v[8];
#pragma unroll
        for (int u = 0; u < 8; u++)
            v[u] = __ldg((const float2*)(g_H1 + (size_t)e[u].x * 64) + lane);
#pragma unroll
        for (int u = 0; u < 8; u++) {
            float wt = __int_as_float(e[u].y);
            acc.x = fmaf(wt, v[u].x, acc.x);
            acc.y = fmaf(wt, v[u].y, acc.y);
        }
    }
    for (; i < cnt; i++) {
        int2 e = __ldg(ep + i);
        float2 v = __ldg((const float2*)(g_H1 + (size_t)e.x * 64) + lane);
        float wt = __int_as_float(e.y);
        acc.x = fmaf(wt, v.x, acc.x); acc.y = fmaf(wt, v.y, acc.y);
    }
    float2 b = __ldg((const float2*)b1 + lane);
    sO[w][lane * 2]     = fmaxf(acc.x + b.x, 0.f);
    sO[w][lane * 2 + 1] = fmaxf(acc.y + b.y, 0.f);
    __syncwarp();

    if (lane < 20) {
        float h0 = 0.f, h1 = 0.f;
        const float* o = sO[w];
#pragma unroll
        for (int k = 0; k < HID; k++) {
            float ov = o[k];
            h0 = fmaf(ov, sW[k * NC + 2 * lane],     h0);
            h1 = fmaf(ov, sW[k * NC + 2 * lane + 1], h1);
        }
        *(float2*)(g_H2 + (size_t)n * NC + lane * 2) = make_float2(h0, h1);
    }
}

// ---------------- gather layer 2 + bias + log_softmax; self-cleans g_deg ----------------
__global__ void __launch_bounds__(256) k_gather2(const float* __restrict__ b2,
                                                 float* __restrict__ out) {
    const int w = threadIdx.x >> 5, lane = threadIdx.x & 31;
    const int n = blockIdx.x * 8 + w;
    const bool act = lane < 20;  // 20 lanes x float2 = 40 cols
    float di = __ldg(g_dinv + n);
    float2 acc = make_float2(0.f, 0.f);
    if (act) {
        acc = __ldg((const float2*)(g_H2 + (size_t)n * NC) + lane);
        acc.x *= di * di; acc.y *= di * di;
    }
    const int start = __ldg(g_rowptr + n);
    const int cnt   = g_deg[n];
    if (lane == 0) g_deg[n] = 0;  // restore zero-invariant for next launch
    const int2* ep = g_edge + start;
    int i = 0;
    for (; i + 8 <= cnt; i += 8) {
        int2 e[8];
#pragma unroll
        for (int u = 0; u < 8; u++) e[u] = __ldg(ep + i + u);
        if (act) {
            float2 v[8];
#pragma unroll
            for (int u = 0; u < 8; u++)
                v[u] = __ldg((const float2*)(g_H2 + (size_t)e[u].x * NC) + lane);
#pragma unroll
            for (int u = 0; u < 8; u++) {
                float wt = __int_as_float(e[u].y);
                acc.x = fmaf(wt, v[u].x, acc.x);
                acc.y = fmaf(wt, v[u].y, acc.y);
            }
        }
    }
    for (; i < cnt; i++) {
        int2 e = __ldg(ep + i);
        if (act) {
            float2 v = __ldg((const float2*)(g_H2 + (size_t)e.x * NC) + lane);
            float wt = __int_as_float(e.y);
            acc.x = fmaf(wt, v.x, acc.x); acc.y = fmaf(wt, v.y, acc.y);
        }
    }
    float2 z = make_float2(-CUDART_INF_F, -CUDART_INF_F);
    if (act) {
        float2 b = __ldg((const float2*)b2 + lane);
        z = make_float2(acc.x + b.x, acc.y + b.y);
    }
    float m = fmaxf(z.x, z.y);
#pragma unroll
    for (int off = 16; off; off >>= 1) m = fmaxf(m, __shfl_xor_sync(0xffffffffu, m, off));
    float s = act ? (__expf(z.x - m) + __expf(z.y - m)) : 0.f;
#pragma unroll
    for (int off = 16; off; off >>= 1) s += __shfl_xor_sync(0xffffffffu, s, off);
    float l = m + __logf(s);
    if (act)
        *(float2*)(out + (size_t)n * NC + lane * 2) = make_float2(z.x - l, z.y - l);
}

// ---------------- launch ----------------
extern "C" void kernel_launch(void* const* d_in, const int* in_sizes, int n_in,
                              void* d_out, int out_size) {
    const float* x  = (const float*)d_in[0];
    const int*   ei = (const int*)d_in[1];
    const float* W1 = (const float*)d_in[2];
    const float* b1 = (const float*)d_in[3];
    const float* W2 = (const float*)d_in[4];
    const float* b2 = (const float*)d_in[5];
    const int* row = ei;         // sources
    const int* col = ei + NE;    // targets
    float* out = (float*)d_out;

    static cudaStream_t s2 = nullptr;
    static cudaEvent_t evFork = nullptr, evJoin = nullptr;
    if (!s2) {  // resolved on the (non-captured) correctness call
        cudaFuncSetAttribute(k_gemm1, cudaFuncAttributeMaxDynamicSharedMemorySize, SM_TOTAL);
        cudaStreamCreateWithFlags(&s2, cudaStreamNonBlocking);
        cudaEventCreateWithFlags(&evFork, cudaEventDisableTiming);
        cudaEventCreateWithFlags(&evJoin, cudaEventDisableTiming);
    }

    // prep node: fused W1 split + degree histogram (g_deg zero by invariant)
    k_prep<<<WSPLIT_NB + HIST_NB, 256>>>(col, W1);

    // fork: stream B runs gemm1 (needs W1h/W1l from prep)
    cudaEventRecord(evFork, 0);
    cudaStreamWaitEvent(s2, evFork, 0);
    k_gemm1<<<(NN + 127) / 128, 256, SM_TOTAL, s2>>>(x);
    cudaEventRecord(evJoin, s2);

    // default stream: CSR scan + fill (needs deg from prep)
    k_scanA<<<SCAN_NB, 256>>>();
    k_scanC<<<SCAN_NB, 256>>>();
    k_fill<<<(NE + 255) / 256, 256>>>(row, col);

    // join, then fused gather1+gemm2 and gather2
    cudaStreamWaitEvent(0, evJoin, 0);
    k_gather1<<<NN / 8, 256>>>(b1, W2);
    k_gather2<<<NN / 8, 256>>>(b2, out);
}

// round 11
// speedup vs baseline: 1.1308x; 1.1308x over previous
#include <cuda_runtime.h>
#include <cuda_bf16.h>
#include <cstdint>
#include <math_constants.h>

// ---------------- problem constants ----------------
static constexpr int NN  = 40000;     // nodes
static constexpr int NE  = 1280000;   // edges
static constexpr int DF  = 1024;      // input feat
static constexpr int HID = 64;        // hidden
static constexpr int NC  = 40;        // classes

// ---------------- device scratch ----------------
__device__ float g_H1[(size_t)NN * HID];   // x @ W1
__device__ float g_H2[(size_t)NN * NC];    // relu(agg1 + b1) @ W2
__device__ float g_dinv[NN];
__device__ int   g_deg[NN];                // in-degree (no self loop)
__device__ int   g_rowptr[NN];             // CSR start per node
__device__ int   g_cursor[NN];
__device__ int   g_rowtmp[NN];             // inclusive scan, pre-base
__device__ int   g_bsum[160];
__device__ int   g_bbase[160];
__device__ int2  g_edge[NE];               // (src, weight-bits) grouped by dst
__device__ __nv_bfloat16 g_W1h[(size_t)HID * DF];  // W1^T hi, [n][k]
__device__ __nv_bfloat16 g_W1l[(size_t)HID * DF];  // W1^T lo, [n][k]

// ---------------- helpers ----------------
__device__ __forceinline__ uint32_t smem_to_u32(const void* p) {
    uint32_t a;
    asm("{ .reg .u64 t; cvta.to.shared.u64 t, %1; cvt.u32.u64 %0, t; }" : "=r"(a) : "l"(p));
    return a;
}
__device__ __forceinline__ uint32_t bfbits(__nv_bfloat16 h) {
    return (uint32_t)__bfloat16_as_ushort(h);
}
#define LDSM4(r, addr) \
    asm volatile("ldmatrix.sync.aligned.m8n8.x4.shared.b16 {%0,%1,%2,%3}, [%4];" \
                 : "=r"((r)[0]), "=r"((r)[1]), "=r"((r)[2]), "=r"((r)[3]) : "r"(addr))
__device__ __forceinline__ void mma16816(float* c, const uint32_t* a, uint32_t b0, uint32_t b1) {
    asm volatile(
        "mma.sync.aligned.m16n8k16.row.col.f32.bf16.bf16.f32 "
        "{%0,%1,%2,%3}, {%4,%5,%6,%7}, {%8,%9}, {%0,%1,%2,%3};"
        : "+f"(c[0]), "+f"(c[1]), "+f"(c[2]), "+f"(c[3])
        : "r"(a[0]), "r"(a[1]), "r"(a[2]), "r"(a[3]), "r"(b0), "r"(b1));
}

// ---------------- prep ----------------
__global__ void k_hist(const int* __restrict__ col) {
    int e = blockIdx.x * blockDim.x + threadIdx.x;
    if (e < NE) atomicAdd(&g_deg[col[e]], 1);
}
__global__ void k_wsplit(const float* __restrict__ W1) {
    int idx = blockIdx.x * blockDim.x + threadIdx.x;
    if (idx >= DF * HID) return;
    int k = idx >> 6, n = idx & 63;
    float w = W1[idx];
    __nv_bfloat16 hi = __float2bfloat16(w);
    float lo = w - __bfloat162float(hi);
    g_W1h[(size_t)n * DF + k] = hi;
    g_W1l[(size_t)n * DF + k] = __float2bfloat16(lo);
}

// ---------------- CSR build: 3-phase scan + fill ----------------
static constexpr int SCAN_NB = (NN + 255) / 256;  // 157
__global__ void k_scanA() {
    __shared__ int s[256];
    int i = blockIdx.x * 256 + threadIdx.x;
    int v = (i < NN) ? g_deg[i] : 0;
    s[threadIdx.x] = v;
    __syncthreads();
#pragma unroll
    for (int off = 1; off < 256; off <<= 1) {
        int t = (threadIdx.x >= off) ? s[threadIdx.x - off] : 0;
        __syncthreads();
        s[threadIdx.x] += t;
        __syncthreads();
    }
    if (i < NN) g_rowtmp[i] = s[threadIdx.x];
    if (threadIdx.x == 255) g_bsum[blockIdx.x] = s[255];
}
__global__ void k_scanB() {
    __shared__ int s[256];
    int v = (threadIdx.x < SCAN_NB) ? g_bsum[threadIdx.x] : 0;
    s[threadIdx.x] = v;
    __syncthreads();
#pragma unroll
    for (int off = 1; off < 256; off <<= 1) {
        int t = (threadIdx.x >= off) ? s[threadIdx.x - off] : 0;
        __syncthreads();
        s[threadIdx.x] += t;
        __syncthreads();
    }
    if (threadIdx.x < SCAN_NB) g_bbase[threadIdx.x] = s[threadIdx.x] - v;  // exclusive
}
__global__ void k_scanC() {  // rowptr/cursor + dinv fused
    int i = blockIdx.x * 256 + threadIdx.x;
    if (i >= NN) return;
    int d = g_deg[i];
    int start = g_rowtmp[i] + g_bbase[blockIdx.x] - d;
    g_rowptr[i] = start;
    g_cursor[i] = start;
    g_dinv[i] = rsqrtf((float)(d + 1));  // +1 self loop
}
__global__ void k_fill(const int* __restrict__ row, const int* __restrict__ col) {
    int e = blockIdx.x * blockDim.x + threadIdx.x;
    if (e >= NE) return;
    int r = __ldg(row + e), c = __ldg(col + e);
    int p = atomicAdd(&g_cursor[c], 1);
    float w = __ldg(g_dinv + r) * __ldg(g_dinv + c);
    g_edge[p] = make_int2(r, __float_as_int(w));
}

// ---------------- GEMM1: mma.sync bf16 hi/lo, M-tile 64, DOUBLE-BUFFERED ----------------
// 625 tiles exactly (40000 = 625*64). One __syncthreads per K-chunk; convert/store of
// chunk k+1 overlaps nothing it shouldn't: stores at iter k+1 hit the buffer last read
// at iter k-1 (separated by the iter-k barrier + program order).
static constexpr int SA_STRIDE = 72;                 // bf16 elems per row (144B)
static constexpr int O_AH = 0;
static constexpr int O_AL = 64 * SA_STRIDE * 2;      // 9216
static constexpr int O_BH = O_AL * 2;                // 18432
static constexpr int O_BL = O_BH + 64 * SA_STRIDE * 2;  // 27648
static constexpr int BUF_SZ = O_BL + 64 * SA_STRIDE * 2; // 36864
static constexpr int SM_TOTAL = 2 * BUF_SZ;          // 73728 -> occ 2 (147KB)

__global__ void __launch_bounds__(256, 2) k_gemm1(const float* __restrict__ x) {
    extern __shared__ char sm[];
    const uint32_t smb = smem_to_u32(sm);
    const int t = threadIdx.x;
    const int lane = t & 31, w = t >> 5;
    const int strip = w >> 1, nhalf = w & 1;
    const int m0 = blockIdx.x * 64;

    // Coalesced A mapping: thread t -> rows {t>>4 + 16i, i<4}, 16B col block c4=t&15.
    const int r0t = t >> 4;
    const int c4  = t & 15;
    const float4* xb = (const float4*)x;
    size_t rbase[4];
    uint32_t aDst[4];
#pragma unroll
    for (int i = 0; i < 4; i++) {
        int rowg = m0 + r0t + 16 * i;
        rbase[i] = (size_t)rowg * 256 + c4;  // float4 units
        aDst[i] = (uint32_t)((r0t + 16 * i) * (SA_STRIDE * 2) + c4 * 8);
    }
    // B load mapping: lin = t + j*256 -> n = lin>>4, q = lin&15
    const uint32_t aLd = smb +
        (uint32_t)((strip * 16 + (lane & 7) + ((lane >> 3) & 1) * 8) * (SA_STRIDE * 2) +
                   (lane >> 4) * 16);
    const uint32_t bLd = smb +
        (uint32_t)((nhalf * 32 + ((lane >> 4) * 8) + (lane & 7)) * (SA_STRIDE * 2) +
                   ((lane >> 3) & 1) * 16);

    float acc[4][4];
#pragma unroll
    for (int j = 0; j < 4; j++)
#pragma unroll
        for (int q = 0; q < 4; q++) acc[j][q] = 0.f;

    // prologue: chunk-0 operands into registers
    float4 pf[4];
    uint2 bh[4], bl[4];
#pragma unroll
    for (int i = 0; i < 4; i++) pf[i] = __ldg(xb + rbase[i]);
#pragma unroll
    for (int j = 0; j < 4; j++) {
        int lin = t + j * 256;
        int n = lin >> 4, q = lin & 15;
        size_t src = (size_t)n * DF + q * 4;
        bh[j] = __ldg((const uint2*)(g_W1h + src));
        bl[j] = __ldg((const uint2*)(g_W1l + src));
    }

    for (int kc = 0; kc < 16; kc++) {
        const uint32_t buf = (uint32_t)((kc & 1) * BUF_SZ);

        // ---- convert & store A chunk kc (from regs) ----
#pragma unroll
        for (int i = 0; i < 4; i++) {
            float4 v = pf[i];
            __nv_bfloat16 hx = __float2bfloat16(v.x), hy = __float2bfloat16(v.y);
            __nv_bfloat16 hz = __float2bfloat16(v.z), hw = __float2bfloat16(v.w);
            *(uint2*)(sm + buf + O_AH + aDst[i]) =
                make_uint2(bfbits(hx) | (bfbits(hy) << 16), bfbits(hz) | (bfbits(hw) << 16));
            __nv_bfloat16 lx = __float2bfloat16(v.x - __bfloat162float(hx));
            __nv_bfloat16 ly = __float2bfloat16(v.y - __bfloat162float(hy));
            __nv_bfloat16 lz = __float2bfloat16(v.z - __bfloat162float(hz));
            __nv_bfloat16 lw = __float2bfloat16(v.w - __bfloat162float(hw));
            *(uint2*)(sm + buf + O_AL + aDst[i]) =
                make_uint2(bfbits(lx) | (bfbits(ly) << 16), bfbits(lz) | (bfbits(lw) << 16));
        }
        // ---- store B chunk kc (from regs) ----
#pragma unroll
        for (int j = 0; j < 4; j++) {
            int lin = t + j * 256;
            int n = lin >> 4, q = lin & 15;
            uint32_t dst = (uint32_t)(n * (SA_STRIDE * 2) + q * 8);
            *(uint2*)(sm + buf + O_BH + dst) = bh[j];
            *(uint2*)(sm + buf + O_BL + dst) = bl[j];
        }
        __syncthreads();

        // ---- issue chunk kc+1 global loads (latency hides under MMA) ----
        if (kc < 15) {
#pragma unroll
            for (int i = 0; i < 4; i++)
                pf[i] = __ldg(xb + rbase[i] + (kc + 1) * 16);
#pragma unroll
            for (int j = 0; j < 4; j++) {
                int lin = t + j * 256;
                int n = lin >> 4, q = lin & 15;
                size_t src = (size_t)n * DF + (kc + 1) * 64 + q * 4;
                bh[j] = __ldg((const uint2*)(g_W1h + src));
                bl[j] = __ldg((const uint2*)(g_W1l + src));
            }
        }

        // ---- MMA on chunk kc: 4 k16 steps x 2 jp (16 n each) x 3 passes ----
#pragma unroll
        for (int ks = 0; ks < 4; ks++) {
            uint32_t ah[4], al[4];
            LDSM4(ah, buf + aLd + O_AH + ks * 32);
            LDSM4(al, buf + aLd + O_AL + ks * 32);
#pragma unroll
            for (int jp = 0; jp < 2; jp++) {
                uint32_t vh[4], vl[4];
                uint32_t boff = (uint32_t)(jp * (16 * SA_STRIDE * 2) + ks * 32);
                LDSM4(vh, buf + bLd + O_BH + boff);
                LDSM4(vl, buf + bLd + O_BL + boff);
                mma16816(acc[2 * jp],     ah, vh[0], vh[1]);
                mma16816(acc[2 * jp],     ah, vl[0], vl[1]);
                mma16816(acc[2 * jp],     al, vh[0], vh[1]);
                mma16816(acc[2 * jp + 1], ah, vh[2], vh[3]);
                mma16816(acc[2 * jp + 1], ah, vl[2], vl[3]);
                mma16816(acc[2 * jp + 1], al, vh[2], vh[3]);
            }
        }
        // no second barrier: next iteration writes the OTHER buffer
    }

    // ---- epilogue (exact tiles, no bounds checks) ----
    const int g = lane >> 2, tig = lane & 3;
    const int r0 = m0 + strip * 16 + g;
    const int r1 = r0 + 8;
#pragma unroll
    for (int nt = 0; nt < 4; nt++) {
        int c = nhalf * 32 + nt * 8 + tig * 2;
        *(float2*)(g_H1 + (size_t)r0 * 64 + c) = make_float2(acc[nt][0], acc[nt][1]);
        *(float2*)(g_H1 + (size_t)r1 * 64 + c) = make_float2(acc[nt][2], acc[nt][3]);
    }
}

// ---------------- gather1 + relu + bias + GEMM2 fused (warp per node) ----------------
__global__ void __launch_bounds__(256) k_gather1(const float* __restrict__ b1,
                                                 const float* __restrict__ W2) {
    __shared__ float sW[HID * NC];   // 10240 B
    __shared__ float sO[8][HID];     // 2048 B
    for (int i = threadIdx.x; i < HID * NC; i += 256) sW[i] = __ldg(W2 + i);
    __syncthreads();

    const int w = threadIdx.x >> 5, lane = threadIdx.x & 31;
    const int n = blockIdx.x * 8 + w;

    float di = __ldg(g_dinv + n);
    float2 acc = __ldg((const float2*)(g_H1 + (size_t)n * 64) + lane);
    acc.x *= di * di; acc.y *= di * di;

    const int start = __ldg(g_rowptr + n);
    const int cnt   = __ldg(g_deg + n);
    const int2* ep = g_edge + start;
    int i = 0;
    for (; i + 8 <= cnt; i += 8) {
        int2 e[8];
#pragma unroll
        for (int u = 0; u < 8; u++) e[u] = __ldg(ep + i + u);
        float2 v[8];
#pragma unroll
        for (int u = 0; u < 8; u++)
            v[u] = __ldg((const float2*)(g_H1 + (size_t)e[u].x * 64) + lane);
#pragma unroll
        for (int u = 0; u < 8; u++) {
            float wt = __int_as_float(e[u].y);
            acc.x = fmaf(wt, v[u].x, acc.x);
            acc.y = fmaf(wt, v[u].y, acc.y);
        }
    }
    for (; i < cnt; i++) {
        int2 e = __ldg(ep + i);
        float2 v = __ldg((const float2*)(g_H1 + (size_t)e.x * 64) + lane);
        float wt = __int_as_float(e.y);
        acc.x = fmaf(wt, v.x, acc.x); acc.y = fmaf(wt, v.y, acc.y);
    }
    float2 b = __ldg((const float2*)b1 + lane);
    sO[w][lane * 2]     = fmaxf(acc.x + b.x, 0.f);
    sO[w][lane * 2 + 1] = fmaxf(acc.y + b.y, 0.f);
    __syncwarp();

    if (lane < 20) {
        float h0 = 0.f, h1 = 0.f;
        const float* o = sO[w];
#pragma unroll
        for (int k = 0; k < HID; k++) {
            float ov = o[k];
            h0 = fmaf(ov, sW[k * NC + 2 * lane],     h0);
            h1 = fmaf(ov, sW[k * NC + 2 * lane + 1], h1);
        }
        *(float2*)(g_H2 + (size_t)n * NC + lane * 2) = make_float2(h0, h1);
    }
}

// ---------------- gather layer 2 + bias + log_softmax (warp per node, MLP 8) ----------------
__global__ void __launch_bounds__(256) k_gather2(const float* __restrict__ b2,
                                                 float* __restrict__ out) {
    const int w = threadIdx.x >> 5, lane = threadIdx.x & 31;
    const int n = blockIdx.x * 8 + w;
    const bool act = lane < 20;  // 20 lanes x float2 = 40 cols
    float di = __ldg(g_dinv + n);
    float2 acc = make_float2(0.f, 0.f);
    if (act) {
        acc = __ldg((const float2*)(g_H2 + (size_t)n * NC) + lane);
        acc.x *= di * di; acc.y *= di * di;
    }
    const int start = __ldg(g_rowptr + n);
    const int cnt   = __ldg(g_deg + n);
    const int2* ep = g_edge + start;
    int i = 0;
    for (; i + 8 <= cnt; i += 8) {
        int2 e[8];
#pragma unroll
        for (int u = 0; u < 8; u++) e[u] = __ldg(ep + i + u);
        if (act) {
            float2 v[8];
#pragma unroll
            for (int u = 0; u < 8; u++)
                v[u] = __ldg((const float2*)(g_H2 + (size_t)e[u].x * NC) + lane);
#pragma unroll
            for (int u = 0; u < 8; u++) {
                float wt = __int_as_float(e[u].y);
                acc.x = fmaf(wt, v[u].x, acc.x);
                acc.y = fmaf(wt, v[u].y, acc.y);
            }
        }
    }
    for (; i < cnt; i++) {
        int2 e = __ldg(ep + i);
        if (act) {
            float2 v = __ldg((const float2*)(g_H2 + (size_t)e.x * NC) + lane);
            float wt = __int_as_float(e.y);
            acc.x = fmaf(wt, v.x, acc.x); acc.y = fmaf(wt, v.y, acc.y);
        }
    }
    float2 z = make_float2(-CUDART_INF_F, -CUDART_INF_F);
    if (act) {
        float2 b = __ldg((const float2*)b2 + lane);
        z = make_float2(acc.x + b.x, acc.y + b.y);
    }
    float m = fmaxf(z.x, z.y);
#pragma unroll
    for (int off = 16; off; off >>= 1) m = fmaxf(m, __shfl_xor_sync(0xffffffffu, m, off));
    float s = act ? (__expf(z.x - m) + __expf(z.y - m)) : 0.f;
#pragma unroll
    for (int off = 16; off; off >>= 1) s += __shfl_xor_sync(0xffffffffu, s, off);
    float l = m + __logf(s);
    if (act)
        *(float2*)(out + (size_t)n * NC + lane * 2) = make_float2(z.x - l, z.y - l);
}

// ---------------- launch ----------------
extern "C" void kernel_launch(void* const* d_in, const int* in_sizes, int n_in,
                              void* d_out, int out_size) {
    const float* x  = (const float*)d_in[0];
    const int*   ei = (const int*)d_in[1];
    const float* W1 = (const float*)d_in[2];
    const float* b1 = (const float*)d_in[3];
    const float* W2 = (const float*)d_in[4];
    const float* b2 = (const float*)d_in[5];
    const int* row = ei;         // sources
    const int* col = ei + NE;    // targets
    float* out = (float*)d_out;

    static void* deg_ptr = nullptr;
    static cudaStream_t s2 = nullptr;
    static cudaEvent_t evFork = nullptr, evJoin = nullptr;
    if (!deg_ptr) {  // resolved on the (non-captured) correctness call
        cudaFuncSetAttribute(k_gemm1, cudaFuncAttributeMaxDynamicSharedMemorySize, SM_TOTAL);
        cudaGetSymbolAddress(&deg_ptr, g_deg);
        cudaStreamCreateWithFlags(&s2, cudaStreamNonBlocking);
        cudaEventCreateWithFlags(&evFork, cudaEventDisableTiming);
        cudaEventCreateWithFlags(&evJoin, cudaEventDisableTiming);
    }

    // fork: stream B runs wsplit + double-buffered gemm1 (independent of CSR chain)
    cudaEventRecord(evFork, 0);
    cudaStreamWaitEvent(s2, evFork, 0);
    k_wsplit<<<(DF * HID + 255) / 256, 256, 0, s2>>>(W1);
    k_gemm1<<<NN / 64, 256, SM_TOTAL, s2>>>(x);
    cudaEventRecord(evJoin, s2);

    // default stream: CSR build chain
    cudaMemsetAsync(deg_ptr, 0, NN * sizeof(int));
    k_hist<<<(NE + 255) / 256, 256>>>(col);
    k_scanA<<<SCAN_NB, 256>>>();
    k_scanB<<<1, 256>>>();
    k_scanC<<<SCAN_NB, 256>>>();
    k_fill<<<(NE + 255) / 256, 256>>>(row, col);

    // join, then fused gather1+gemm2 and gather2
    cudaStreamWaitEvent(0, evJoin, 0);
    k_gather1<<<NN / 8, 256>>>(b1, W2);
    k_gather2<<<NN / 8, 256>>>(b2, out);
}

// round 12
// speedup vs baseline: 1.1432x; 1.0110x over previous
#include <cuda_runtime.h>
#include <cuda_bf16.h>
#include <cuda_fp16.h>
#include <cstdint>
#include <math_constants.h>

// ---------------- problem constants ----------------
static constexpr int NN  = 40000;     // nodes
static constexpr int NE  = 1280000;   // edges
static constexpr int DF  = 1024;      // input feat
static constexpr int HID = 64;        // hidden
static constexpr int NC  = 40;        // classes

// ---------------- device scratch ----------------
__device__ float  g_H1[(size_t)NN * HID];   // x @ W1 (fp32, self-term)
__device__ __half g_H1h[(size_t)NN * HID];  // fp16 mirror for neighbor gathers
__device__ float  g_H2[(size_t)NN * NC];    // relu(agg1 + b1) @ W2
__device__ float  g_dinv[NN];
__device__ int    g_deg[NN];                // in-degree (no self loop)
__device__ int    g_rowptr[NN];             // CSR start per node
__device__ int    g_cursor[NN];
__device__ int    g_rowtmp[NN];             // inclusive scan, pre-base
__device__ int    g_bsum[160];
__device__ int    g_bbase[160];
__device__ int2   g_edge[NE];               // (src, weight-bits) grouped by dst
__device__ __nv_bfloat16 g_W1h[(size_t)HID * DF];  // W1^T hi, [n][k]
__device__ __nv_bfloat16 g_W1l[(size_t)HID * DF];  // W1^T lo, [n][k]

// ---------------- helpers ----------------
__device__ __forceinline__ uint32_t smem_to_u32(const void* p) {
    uint32_t a;
    asm("{ .reg .u64 t; cvta.to.shared.u64 t, %1; cvt.u32.u64 %0, t; }" : "=r"(a) : "l"(p));
    return a;
}
__device__ __forceinline__ uint32_t bfbits(__nv_bfloat16 h) {
    return (uint32_t)__bfloat16_as_ushort(h);
}
#define LDSM4(r, addr) \
    asm volatile("ldmatrix.sync.aligned.m8n8.x4.shared.b16 {%0,%1,%2,%3}, [%4];" \
                 : "=r"((r)[0]), "=r"((r)[1]), "=r"((r)[2]), "=r"((r)[3]) : "r"(addr))
__device__ __forceinline__ void mma16816(float* c, const uint32_t* a, uint32_t b0, uint32_t b1) {
    asm volatile(
        "mma.sync.aligned.m16n8k16.row.col.f32.bf16.bf16.f32 "
        "{%0,%1,%2,%3}, {%4,%5,%6,%7}, {%8,%9}, {%0,%1,%2,%3};"
        : "+f"(c[0]), "+f"(c[1]), "+f"(c[2]), "+f"(c[3])
        : "r"(a[0]), "r"(a[1]), "r"(a[2]), "r"(a[3]), "r"(b0), "r"(b1));
}

// ---------------- prep ----------------
__global__ void k_hist(const int* __restrict__ col) {
    int e = blockIdx.x * blockDim.x + threadIdx.x;
    if (e < NE) atomicAdd(&g_deg[col[e]], 1);
}
__global__ void k_wsplit(const float* __restrict__ W1) {
    int idx = blockIdx.x * blockDim.x + threadIdx.x;
    if (idx >= DF * HID) return;
    int k = idx >> 6, n = idx & 63;
    float w = W1[idx];
    __nv_bfloat16 hi = __float2bfloat16(w);
    float lo = w - __bfloat162float(hi);
    g_W1h[(size_t)n * DF + k] = hi;
    g_W1l[(size_t)n * DF + k] = __float2bfloat16(lo);
}

// ---------------- CSR build: 3-phase scan + fill ----------------
static constexpr int SCAN_NB = (NN + 255) / 256;  // 157
__global__ void k_scanA() {
    __shared__ int s[256];
    int i = blockIdx.x * 256 + threadIdx.x;
    int v = (i < NN) ? g_deg[i] : 0;
    s[threadIdx.x] = v;
    __syncthreads();
#pragma unroll
    for (int off = 1; off < 256; off <<= 1) {
        int t = (threadIdx.x >= off) ? s[threadIdx.x - off] : 0;
        __syncthreads();
        s[threadIdx.x] += t;
        __syncthreads();
    }
    if (i < NN) g_rowtmp[i] = s[threadIdx.x];
    if (threadIdx.x == 255) g_bsum[blockIdx.x] = s[255];
}
__global__ void k_scanB() {
    __shared__ int s[256];
    int v = (threadIdx.x < SCAN_NB) ? g_bsum[threadIdx.x] : 0;
    s[threadIdx.x] = v;
    __syncthreads();
#pragma unroll
    for (int off = 1; off < 256; off <<= 1) {
        int t = (threadIdx.x >= off) ? s[threadIdx.x - off] : 0;
        __syncthreads();
        s[threadIdx.x] += t;
        __syncthreads();
    }
    if (threadIdx.x < SCAN_NB) g_bbase[threadIdx.x] = s[threadIdx.x] - v;  // exclusive
}
__global__ void k_scanC() {  // rowptr/cursor + dinv fused
    int i = blockIdx.x * 256 + threadIdx.x;
    if (i >= NN) return;
    int d = g_deg[i];
    int start = g_rowtmp[i] + g_bbase[blockIdx.x] - d;
    g_rowptr[i] = start;
    g_cursor[i] = start;
    g_dinv[i] = rsqrtf((float)(d + 1));  // +1 self loop
}
__global__ void k_fill(const int* __restrict__ row, const int* __restrict__ col) {
    int e = blockIdx.x * blockDim.x + threadIdx.x;
    if (e >= NE) return;
    int r = __ldg(row + e), c = __ldg(col + e);
    int p = atomicAdd(&g_cursor[c], 1);
    float w = __ldg(g_dinv + r) * __ldg(g_dinv + c);
    g_edge[p] = make_int2(r, __float_as_int(w));
}

// ---------------- GEMM1: mma.sync bf16 hi/lo, M-tile 64, DOUBLE-BUFFERED ----------------
static constexpr int SA_STRIDE = 72;                 // bf16 elems per row (144B)
static constexpr int O_AH = 0;
static constexpr int O_AL = 64 * SA_STRIDE * 2;      // 9216
static constexpr int O_BH = O_AL * 2;                // 18432
static constexpr int O_BL = O_BH + 64 * SA_STRIDE * 2;  // 27648
static constexpr int BUF_SZ = O_BL + 64 * SA_STRIDE * 2; // 36864
static constexpr int SM_TOTAL = 2 * BUF_SZ;          // 73728 -> occ 2 (147KB)

__global__ void __launch_bounds__(256, 2) k_gemm1(const float* __restrict__ x) {
    extern __shared__ char sm[];
    const uint32_t smb = smem_to_u32(sm);
    const int t = threadIdx.x;
    const int lane = t & 31, w = t >> 5;
    const int strip = w >> 1, nhalf = w & 1;
    const int m0 = blockIdx.x * 64;

    const int r0t = t >> 4;
    const int c4  = t & 15;
    const float4* xb = (const float4*)x;
    size_t rbase[4];
    uint32_t aDst[4];
#pragma unroll
    for (int i = 0; i < 4; i++) {
        int rowg = m0 + r0t + 16 * i;
        rbase[i] = (size_t)rowg * 256 + c4;  // float4 units
        aDst[i] = (uint32_t)((r0t + 16 * i) * (SA_STRIDE * 2) + c4 * 8);
    }
    const uint32_t aLd = smb +
        (uint32_t)((strip * 16 + (lane & 7) + ((lane >> 3) & 1) * 8) * (SA_STRIDE * 2) +
                   (lane >> 4) * 16);
    const uint32_t bLd = smb +
        (uint32_t)((nhalf * 32 + ((lane >> 4) * 8) + (lane & 7)) * (SA_STRIDE * 2) +
                   ((lane >> 3) & 1) * 16);

    float acc[4][4];
#pragma unroll
    for (int j = 0; j < 4; j++)
#pragma unroll
        for (int q = 0; q < 4; q++) acc[j][q] = 0.f;

    // prologue: chunk-0 operands into registers
    float4 pf[4];
    uint2 bh[4], bl[4];
#pragma unroll
    for (int i = 0; i < 4; i++) pf[i] = __ldg(xb + rbase[i]);
#pragma unroll
    for (int j = 0; j < 4; j++) {
        int lin = t + j * 256;
        int n = lin >> 4, q = lin & 15;
        size_t src = (size_t)n * DF + q * 4;
        bh[j] = __ldg((const uint2*)(g_W1h + src));
        bl[j] = __ldg((const uint2*)(g_W1l + src));
    }

    for (int kc = 0; kc < 16; kc++) {
        const uint32_t buf = (uint32_t)((kc & 1) * BUF_SZ);

        // ---- convert & store A chunk kc (from regs) ----
#pragma unroll
        for (int i = 0; i < 4; i++) {
            float4 v = pf[i];
            __nv_bfloat16 hx = __float2bfloat16(v.x), hy = __float2bfloat16(v.y);
            __nv_bfloat16 hz = __float2bfloat16(v.z), hw = __float2bfloat16(v.w);
            *(uint2*)(sm + buf + O_AH + aDst[i]) =
                make_uint2(bfbits(hx) | (bfbits(hy) << 16), bfbits(hz) | (bfbits(hw) << 16));
            __nv_bfloat16 lx = __float2bfloat16(v.x - __bfloat162float(hx));
            __nv_bfloat16 ly = __float2bfloat16(v.y - __bfloat162float(hy));
            __nv_bfloat16 lz = __float2bfloat16(v.z - __bfloat162float(hz));
            __nv_bfloat16 lw = __float2bfloat16(v.w - __bfloat162float(hw));
            *(uint2*)(sm + buf + O_AL + aDst[i]) =
                make_uint2(bfbits(lx) | (bfbits(ly) << 16), bfbits(lz) | (bfbits(lw) << 16));
        }
        // ---- store B chunk kc (from regs) ----
#pragma unroll
        for (int j = 0; j < 4; j++) {
            int lin = t + j * 256;
            int n = lin >> 4, q = lin & 15;
            uint32_t dst = (uint32_t)(n * (SA_STRIDE * 2) + q * 8);
            *(uint2*)(sm + buf + O_BH + dst) = bh[j];
            *(uint2*)(sm + buf + O_BL + dst) = bl[j];
        }
        __syncthreads();

        // ---- issue chunk kc+1 global loads (latency hides under MMA) ----
        if (kc < 15) {
#pragma unroll
            for (int i = 0; i < 4; i++)
                pf[i] = __ldg(xb + rbase[i] + (kc + 1) * 16);
#pragma unroll
            for (int j = 0; j < 4; j++) {
                int lin = t + j * 256;
                int n = lin >> 4, q = lin & 15;
                size_t src = (size_t)n * DF + (kc + 1) * 64 + q * 4;
                bh[j] = __ldg((const uint2*)(g_W1h + src));
                bl[j] = __ldg((const uint2*)(g_W1l + src));
            }
        }

        // ---- MMA on chunk kc ----
#pragma unroll
        for (int ks = 0; ks < 4; ks++) {
            uint32_t ah[4], al[4];
            LDSM4(ah, buf + aLd + O_AH + ks * 32);
            LDSM4(al, buf + aLd + O_AL + ks * 32);
#pragma unroll
            for (int jp = 0; jp < 2; jp++) {
                uint32_t vh[4], vl[4];
                uint32_t boff = (uint32_t)(jp * (16 * SA_STRIDE * 2) + ks * 32);
                LDSM4(vh, buf + bLd + O_BH + boff);
                LDSM4(vl, buf + bLd + O_BL + boff);
                mma16816(acc[2 * jp],     ah, vh[0], vh[1]);
                mma16816(acc[2 * jp],     ah, vl[0], vl[1]);
                mma16816(acc[2 * jp],     al, vh[0], vh[1]);
                mma16816(acc[2 * jp + 1], ah, vh[2], vh[3]);
                mma16816(acc[2 * jp + 1], ah, vl[2], vl[3]);
                mma16816(acc[2 * jp + 1], al, vh[2], vh[3]);
            }
        }
        // no second barrier: next iteration writes the OTHER buffer
    }

    // ---- epilogue: fp32 + fp16 mirror ----
    const int g = lane >> 2, tig = lane & 3;
    const int r0 = m0 + strip * 16 + g;
    const int r1 = r0 + 8;
#pragma unroll
    for (int nt = 0; nt < 4; nt++) {
        int c = nhalf * 32 + nt * 8 + tig * 2;
        *(float2*)(g_H1 + (size_t)r0 * 64 + c) = make_float2(acc[nt][0], acc[nt][1]);
        *(float2*)(g_H1 + (size_t)r1 * 64 + c) = make_float2(acc[nt][2], acc[nt][3]);
        *(__half2*)(g_H1h + (size_t)r0 * 64 + c) = __floats2half2_rn(acc[nt][0], acc[nt][1]);
        *(__half2*)(g_H1h + (size_t)r1 * 64 + c) = __floats2half2_rn(acc[nt][2], acc[nt][3]);
    }
}

// ---------------- gather1 + relu + bias + GEMM2 fused (warp per node) ----------------
// Neighbor rows gathered from fp16 mirror (128B/row); self-term + math in fp32.
__global__ void __launch_bounds__(256) k_gather1(const float* __restrict__ b1,
                                                 const float* __restrict__ W2) {
    __shared__ float sW[HID * NC];   // 10240 B
    __shared__ float sO[8][HID];     // 2048 B
    for (int i = threadIdx.x; i < HID * NC; i += 256) sW[i] = __ldg(W2 + i);
    __syncthreads();

    const int w = threadIdx.x >> 5, lane = threadIdx.x & 31;
    const int n = blockIdx.x * 8 + w;

    float di = __ldg(g_dinv + n);
    float2 acc = __ldg((const float2*)(g_H1 + (size_t)n * 64) + lane);
    acc.x *= di * di; acc.y *= di * di;

    const int start = __ldg(g_rowptr + n);
    const int cnt   = __ldg(g_deg + n);
    const int2* ep = g_edge + start;
    int i = 0;
    for (; i + 8 <= cnt; i += 8) {
        int2 e[8];
#pragma unroll
        for (int u = 0; u < 8; u++) e[u] = __ldg(ep + i + u);
        __half2 v[8];
#pragma unroll
        for (int u = 0; u < 8; u++)
            v[u] = __ldg((const __half2*)(g_H1h + (size_t)e[u].x * 64) + lane);
#pragma unroll
        for (int u = 0; u < 8; u++) {
            float wt = __int_as_float(e[u].y);
            float2 f = __half22float2(v[u]);
            acc.x = fmaf(wt, f.x, acc.x);
            acc.y = fmaf(wt, f.y, acc.y);
        }
    }
    for (; i < cnt; i++) {
        int2 e = __ldg(ep + i);
        __half2 v = __ldg((const __half2*)(g_H1h + (size_t)e.x * 64) + lane);
        float wt = __int_as_float(e.y);
        float2 f = __half22float2(v);
        acc.x = fmaf(wt, f.x, acc.x); acc.y = fmaf(wt, f.y, acc.y);
    }
    float2 b = __ldg((const float2*)b1 + lane);
    sO[w][lane * 2]     = fmaxf(acc.x + b.x, 0.f);
    sO[w][lane * 2 + 1] = fmaxf(acc.y + b.y, 0.f);
    __syncwarp();

    if (lane < 20) {
        float h0 = 0.f, h1 = 0.f;
        const float* o = sO[w];
#pragma unroll
        for (int k = 0; k < HID; k++) {
            float ov = o[k];
            h0 = fmaf(ov, sW[k * NC + 2 * lane],     h0);
            h1 = fmaf(ov, sW[k * NC + 2 * lane + 1], h1);
        }
        *(float2*)(g_H2 + (size_t)n * NC + lane * 2) = make_float2(h0, h1);
    }
}

// ---------------- gather layer 2 + bias + log_softmax (warp per node, MLP 8) ----------------
__global__ void __launch_bounds__(256) k_gather2(const float* __restrict__ b2,
                                                 float* __restrict__ out) {
    const int w = threadIdx.x >> 5, lane = threadIdx.x & 31;
    const int n = blockIdx.x * 8 + w;
    const bool act = lane < 20;  // 20 lanes x float2 = 40 cols
    float di = __ldg(g_dinv + n);
    float2 acc = make_float2(0.f, 0.f);
    if (act) {
        acc = __ldg((const float2*)(g_H2 + (size_t)n * NC) + lane);
        acc.x *= di * di; acc.y *= di * di;
    }
    const int start = __ldg(g_rowptr + n);
    const int cnt   = __ldg(g_deg + n);
    const int2* ep = g_edge + start;
    int i = 0;
    for (; i + 8 <= cnt; i += 8) {
        int2 e[8];
#pragma unroll
        for (int u = 0; u < 8; u++) e[u] = __ldg(ep + i + u);
        if (act) {
            float2 v[8];
#pragma unroll
            for (int u = 0; u < 8; u++)
                v[u] = __ldg((const float2*)(g_H2 + (size_t)e[u].x * NC) + lane);
#pragma unroll
            for (int u = 0; u < 8; u++) {
                float wt = __int_as_float(e[u].y);
                acc.x = fmaf(wt, v[u].x, acc.x);
                acc.y = fmaf(wt, v[u].y, acc.y);
            }
        }
    }
    for (; i < cnt; i++) {
        int2 e = __ldg(ep + i);
        if (act) {
            float2 v = __ldg((const float2*)(g_H2 + (size_t)e.x * NC) + lane);
            float wt = __int_as_float(e.y);
            acc.x = fmaf(wt, v.x, acc.x); acc.y = fmaf(wt, v.y, acc.y);
        }
    }
    float2 z = make_float2(-CUDART_INF_F, -CUDART_INF_F);
    if (act) {
        float2 b = __ldg((const float2*)b2 + lane);
        z = make_float2(acc.x + b.x, acc.y + b.y);
    }
    float m = fmaxf(z.x, z.y);
#pragma unroll
    for (int off = 16; off; off >>= 1) m = fmaxf(m, __shfl_xor_sync(0xffffffffu, m, off));
    float s = act ? (__expf(z.x - m) + __expf(z.y - m)) : 0.f;
#pragma unroll
    for (int off = 16; off; off >>= 1) s += __shfl_xor_sync(0xffffffffu, s, off);
    float l = m + __logf(s);
    if (act)
        *(float2*)(out + (size_t)n * NC + lane * 2) = make_float2(z.x - l, z.y - l);
}

// ---------------- launch ----------------
extern "C" void kernel_launch(void* const* d_in, const int* in_sizes, int n_in,
                              void* d_out, int out_size) {
    const float* x  = (const float*)d_in[0];
    const int*   ei = (const int*)d_in[1];
    const float* W1 = (const float*)d_in[2];
    const float* b1 = (const float*)d_in[3];
    const float* W2 = (const float*)d_in[4];
    const float* b2 = (const float*)d_in[5];
    const int* row = ei;         // sources
    const int* col = ei + NE;    // targets
    float* out = (float*)d_out;

    static void* deg_ptr = nullptr;
    static cudaStream_t s2 = nullptr;
    static cudaEvent_t evFork = nullptr, evJoin = nullptr;
    if (!deg_ptr) {  // resolved on the (non-captured) correctness call
        cudaFuncSetAttribute(k_gemm1, cudaFuncAttributeMaxDynamicSharedMemorySize, SM_TOTAL);
        cudaGetSymbolAddress(&deg_ptr, g_deg);
        cudaStreamCreateWithFlags(&s2, cudaStreamNonBlocking);
        cudaEventCreateWithFlags(&evFork, cudaEventDisableTiming);
        cudaEventCreateWithFlags(&evJoin, cudaEventDisableTiming);
    }

    // fork: stream B runs wsplit + double-buffered gemm1 (independent of CSR chain)
    cudaEventRecord(evFork, 0);
    cudaStreamWaitEvent(s2, evFork, 0);
    k_wsplit<<<(DF * HID + 255) / 256, 256, 0, s2>>>(W1);
    k_gemm1<<<NN / 64, 256, SM_TOTAL, s2>>>(x);
    cudaEventRecord(evJoin, s2);

    // default stream: CSR build chain
    cudaMemsetAsync(deg_ptr, 0, NN * sizeof(int));
    k_hist<<<(NE + 255) / 256, 256>>>(col);
    k_scanA<<<SCAN_NB, 256>>>();
    k_scanB<<<1, 256>>>();
    k_scanC<<<SCAN_NB, 256>>>();
    k_fill<<<(NE + 255) / 256, 256>>>(row, col);

    // join, then fused gather1+gemm2 and gather2
    cudaStreamWaitEvent(0, evJoin, 0);
    k_gather1<<<NN / 8, 256>>>(b1, W2);
    k_gather2<<<NN / 8, 256>>>(b2, out);
}